// round 2
// baseline (speedup 1.0000x reference)
#include <cuda_runtime.h>
#include <cstdint>

#define Bn 16
#define Hh 512
#define Ww 512
#define IMG (Hh*Ww)            // 262144 = 2^18
#define NPX (Bn*IMG)           // 4194304
#define TPI 256                // (512/32)^2 tiles per image
#define NTILES (Bn*TPI)        // 4096
#define WARPS 16
#define THREADS (WARPS*32)     // 512
#define SM_STRIDE 35           // 34 cols padded to 35
#define SM_SZ (34*SM_STRIDE)
#define MK_STRIDE 33
#define MK_SZ (32*MK_STRIDE)
#define WARP_SMEM (SM_SZ + MK_SZ)
#define SMEM_BYTES (WARPS*WARP_SMEM*4)
#define MAX_PASSES 4096
#define MAX_TILE_ITERS 1024

// ---- device globals (static scratch; no dynamic allocation) ----
__device__ float g_bufA[NPX];          // xh
__device__ float g_bufB[NPX];          // rec2 -> Rmax
__device__ float g_bufC[NPX];          // M -> R
__device__ int   g_tile_epoch[NTILES];
__device__ volatile int g_flag;
__device__ unsigned g_cc[Bn];
__device__ int g_hasone, g_haszero;
__device__ unsigned g_bar_count = 0;
__device__ volatile unsigned g_bar_gen = 0;

// ---- software grid barrier (all blocks resident: 1 block/SM via smem) ----
__device__ __forceinline__ void grid_sync(int nb) {
    __syncthreads();
    if (threadIdx.x == 0) {
        __threadfence();
        unsigned gen = g_bar_gen;
        unsigned t = atomicAdd(&g_bar_count, 1u);
        if (t == (unsigned)nb - 1u) {
            atomicExch(&g_bar_count, 0u);
            __threadfence();
            g_bar_gen = gen + 1u;
        } else {
            while (g_bar_gen == gen) { __nanosleep(128); }
        }
        __threadfence();
    }
    __syncthreads();
}

__device__ __forceinline__ float f3max(float a, float b, float c) {
    return fmaxf(fmaxf(a, b), c);
}

// ---- warp-local tile relaxation to fixpoint ----
__device__ void process_tile(int t, float* m, const float* mask,
                             volatile float* sm, float* smk, int lane, int epoch) {
    const int b   = t >> 8;
    const int r   = t & 255;
    const int ty0 = (r >> 4) << 5;
    const int tx0 = (r & 15) << 5;
    const size_t base = ((size_t)b) << 18;
    const float NEGINF = __int_as_float(0xff800000);

    // load marker tile + 1-px halo (out-of-image -> -inf)
    for (int i = lane; i < 34 * 34; i += 32) {
        int yy = i / 34, xx = i - yy * 34;
        int gy = ty0 + yy - 1, gx = tx0 + xx - 1;
        float v = NEGINF;
        if ((unsigned)gy < 512u && (unsigned)gx < 512u)
            v = __ldcg(m + base + ((size_t)gy << 9) + gx);
        sm[yy * SM_STRIDE + xx] = v;
    }
    // load mask (interior only)
    for (int i = lane; i < 1024; i += 32) {
        int yy = i >> 5, xx = i & 31;
        smk[yy * MK_STRIDE + xx] =
            __ldcg(mask + base + ((size_t)(ty0 + yy) << 9) + (tx0 + xx));
    }
    __syncwarp();

    int any = 0;
    for (int it = 0; it < MAX_TILE_ITERS; it++) {
        int ch = 0;
        // DOWN sweep: lane = column
        {
            const int xx = lane;
            #pragma unroll 1
            for (int yy = 0; yy < 32; yy++) {
                float up  = f3max(sm[yy*SM_STRIDE + xx], sm[yy*SM_STRIDE + xx + 1], sm[yy*SM_STRIDE + xx + 2]);
                float cur = sm[(yy+1)*SM_STRIDE + xx + 1];
                float nv  = fminf(fmaxf(cur, up), smk[yy*MK_STRIDE + xx]);
                if (nv > cur) { sm[(yy+1)*SM_STRIDE + xx + 1] = nv; ch = 1; }
                __syncwarp();
            }
        }
        // UP sweep
        {
            const int xx = lane;
            #pragma unroll 1
            for (int yy = 31; yy >= 0; yy--) {
                float dn  = f3max(sm[(yy+2)*SM_STRIDE + xx], sm[(yy+2)*SM_STRIDE + xx + 1], sm[(yy+2)*SM_STRIDE + xx + 2]);
                float cur = sm[(yy+1)*SM_STRIDE + xx + 1];
                float nv  = fminf(fmaxf(cur, dn), smk[yy*MK_STRIDE + xx]);
                if (nv > cur) { sm[(yy+1)*SM_STRIDE + xx + 1] = nv; ch = 1; }
                __syncwarp();
            }
        }
        // RIGHT sweep (x increasing): lane = row
        {
            const int yy = lane;
            #pragma unroll 1
            for (int xx = 0; xx < 32; xx++) {
                float lf  = f3max(sm[yy*SM_STRIDE + xx], sm[(yy+1)*SM_STRIDE + xx], sm[(yy+2)*SM_STRIDE + xx]);
                float cur = sm[(yy+1)*SM_STRIDE + xx + 1];
                float nv  = fminf(fmaxf(cur, lf), smk[yy*MK_STRIDE + xx]);
                if (nv > cur) { sm[(yy+1)*SM_STRIDE + xx + 1] = nv; ch = 1; }
                __syncwarp();
            }
        }
        // LEFT sweep
        {
            const int yy = lane;
            #pragma unroll 1
            for (int xx = 31; xx >= 0; xx--) {
                float rt  = f3max(sm[yy*SM_STRIDE + xx + 2], sm[(yy+1)*SM_STRIDE + xx + 2], sm[(yy+2)*SM_STRIDE + xx + 2]);
                float cur = sm[(yy+1)*SM_STRIDE + xx + 1];
                float nv  = fminf(fmaxf(cur, rt), smk[yy*MK_STRIDE + xx]);
                if (nv > cur) { sm[(yy+1)*SM_STRIDE + xx + 1] = nv; ch = 1; }
                __syncwarp();
            }
        }
        if (__any_sync(0xffffffffu, ch)) any = 1; else break;
    }

    if (any) {
        for (int i = lane; i < 1024; i += 32) {
            int yy = i >> 5, xx = i & 31;
            __stcg(m + base + ((size_t)(ty0 + yy) << 9) + (tx0 + xx),
                   sm[(yy+1)*SM_STRIDE + xx + 1]);
        }
        if (lane == 0) {
            ((volatile int*)g_tile_epoch)[t] = epoch;
            g_flag = epoch;
        }
    }
}

// ---- global reconstruction: repeat passes until no tile changes ----
__device__ void reconstruct(float* m, const float* mask, int nb, int& epoch,
                            volatile float* sm, float* smk) {
    const int wid  = threadIdx.x >> 5;
    const int lane = threadIdx.x & 31;
    const int wslots = nb * WARPS;
    bool first = true;
    for (int pass = 0; pass < MAX_PASSES; pass++) {
        epoch++;
        for (int t = blockIdx.x * WARPS + wid; t < NTILES; t += wslots) {
            if (!first) {
                int need = 0;
                if (lane < 9 && lane != 4) {      // 8 neighbor tiles
                    int dy = lane / 3 - 1, dx = lane % 3 - 1;
                    int b = t >> 8, r = t & 255;
                    int ny = (r >> 4) + dy, nx = (r & 15) + dx;
                    if ((unsigned)ny < 16u && (unsigned)nx < 16u)
                        need = (((volatile int*)g_tile_epoch)[(b << 8) + (ny << 4) + nx] >= (epoch - 1));
                }
                if (!__any_sync(0xffffffffu, need)) continue;
            }
            process_tile(t, m, mask, sm, smk, lane, epoch);
        }
        grid_sync(nb);
        int f = g_flag;      // volatile read; stable between the two barriers
        grid_sync(nb);
        if (f != epoch) break;
        first = false;
    }
}

__global__ void __launch_bounds__(THREADS, 1)
mega(const float* __restrict__ x, const float* __restrict__ hh,
     const float* __restrict__ u, float* __restrict__ out,
     int nb, int xh_off, int write_cc)
{
    extern __shared__ float dynsm[];
    const int wid  = threadIdx.x >> 5;
    const int lane = threadIdx.x & 31;
    volatile float* sm = dynsm + (size_t)wid * WARP_SMEM;
    float* smk = (float*)(dynsm + (size_t)wid * WARP_SMEM + SM_SZ);
    const int gtid = blockIdx.x * THREADS + threadIdx.x;
    const int nt   = nb * THREADS;

    // ---- reset per-launch state + phase A init: marker = x - h[b], mask = x
    for (int i = gtid; i < NTILES; i += nt) g_tile_epoch[i] = 0;
    if (gtid < Bn) g_cc[gtid] = 0u;
    if (gtid == 0) { g_flag = 0; g_hasone = 0; g_haszero = 0; }
    for (int i = gtid; i < NPX; i += nt) {
        float hv = __ldg(hh + (i >> 18));
        __stcg(g_bufA + i, x[i] - hv);
    }
    grid_sync(nb);

    int epoch = 0;
    // xh = reconstruct(x - h, x)
    reconstruct(g_bufA, x, nb, epoch, sm, smk);

    // ---- write xh to output; marker2 = xh - eps
    for (int i = gtid; i < NPX; i += nt) {
        float v = __ldcg(g_bufA + i);
        out[xh_off + i] = v;
        __stcg(g_bufB + i, v - 1e-5f);
    }
    grid_sync(nb);
    // rec2 = reconstruct(xh - eps, xh)
    reconstruct(g_bufB, g_bufA, nb, epoch, sm, smk);

    // ---- Rmax = (xh - rec2 > 0); M = min(u, Rmax); track global max/min of Rmax
    int one = 0, zero = 0;
    for (int i = gtid; i < NPX; i += nt) {
        float rec = __ldcg(g_bufB + i);
        float xh  = __ldcg(g_bufA + i);
        float rmx = ((xh - rec) > 0.0f) ? 1.0f : 0.0f;
        if (rmx != 0.0f) one = 1; else zero = 1;
        __stcg(g_bufB + i, rmx);
        __stcg(g_bufC + i, fminf(u[i], rmx));
    }
    if (__any_sync(0xffffffffu, one)  && lane == 0) atomicOr(&g_hasone, 1);
    if (__any_sync(0xffffffffu, zero) && lane == 0) atomicOr(&g_haszero, 1);
    grid_sync(nb);
    // R = reconstruct(M, Rmax)
    reconstruct(g_bufC, g_bufB, nb, epoch, sm, smk);

    // ---- Detection = (u == R); CC[b] = sum  (exact integer counts)
    __shared__ unsigned s_cnt[Bn];
    if (threadIdx.x < Bn) s_cnt[threadIdx.x] = 0u;
    __syncthreads();
    for (int i = gtid; i < NPX; i += nt) {
        if (u[i] == __ldcg(g_bufC + i)) atomicAdd(&s_cnt[i >> 18], 1u);
    }
    __syncthreads();
    if (threadIdx.x < Bn && s_cnt[threadIdx.x])
        atomicAdd(&g_cc[threadIdx.x], s_cnt[threadIdx.x]);
    grid_sync(nb);

    if (write_cc && blockIdx.x == 0 && threadIdx.x < Bn) {
        int ho = ((volatile int*)&g_hasone)[0];
        int hz = ((volatile int*)&g_haszero)[0];
        float d  = (ho && hz) ? 1.0f : 0.0f;   // max(Rmax) - min(Rmax)
        float cc = (float)((volatile unsigned*)g_cc)[threadIdx.x];
        out[threadIdx.x] = fminf(cc, 100.0f * d * cc);
    }
}

extern "C" void kernel_launch(void* const* d_in, const int* in_sizes, int n_in,
                              void* d_out, int out_size) {
    const float* x = (const float*)d_in[0];
    const float* h = (const float*)d_in[1];
    const float* u = (const float*)d_in[2];
    float* out = (float*)d_out;

    int dev = 0;
    cudaGetDevice(&dev);
    int sms = 0;
    cudaDeviceGetAttribute(&sms, cudaDevAttrMultiProcessorCount, dev);
    if (sms <= 0) sms = 148;

    cudaFuncSetAttribute(mega, cudaFuncAttributeMaxDynamicSharedMemorySize, SMEM_BYTES);
    int occ = 0;
    cudaOccupancyMaxActiveBlocksPerMultiprocessor(&occ, mega, THREADS, SMEM_BYTES);
    if (occ < 1) occ = 1;
    int nb = sms * occ;   // all blocks resident -> software grid barrier is safe

    int xh_off = out_size - NPX;          // tuple layout: [CC_(16) | xh(N)]
    int write_cc = (xh_off >= Bn) ? 1 : 0;
    if (xh_off < 0) xh_off = 0;

    mega<<<nb, THREADS, SMEM_BYTES>>>(x, h, u, out, nb, xh_off, write_cc);
}